// round 4
// baseline (speedup 1.0000x reference)
#include <cuda_runtime.h>
#include <math.h>

#define NPTS 1024
#define NF   32     // frequency pairs (sin+cos => 64 features)
#define NH   16     // heads

// ---- packed f32x2 helpers (Blackwell FFMA2 path) ----
__device__ __forceinline__ unsigned long long pack_dup(float x) {
    unsigned long long r;
    asm("mov.b64 %0, {%1, %1};" : "=l"(r) : "f"(x));
    return r;
}
__device__ __forceinline__ unsigned long long pack2(float lo, float hi) {
    unsigned long long r;
    asm("mov.b64 %0, {%1, %2};" : "=l"(r) : "f"(lo), "f"(hi));
    return r;
}
__device__ __forceinline__ void fma2(unsigned long long& d,
                                     unsigned long long a,
                                     unsigned long long b) {
    asm("fma.rn.f32x2 %0, %1, %2, %0;" : "+l"(d) : "l"(a), "l"(b));
}
__device__ __forceinline__ float2 unpack2(unsigned long long v) {
    float lo, hi;
    asm("mov.b64 {%0, %1}, %2;" : "=f"(lo), "=f"(hi) : "l"(v));
    return make_float2(lo, hi);
}

// Fully fused kernel. Block = rows (i, i+512) of batch b.
// - cooperatively normalizes all 1024 vectors of batch b into SMEM
// - thread tid handles 4 pairs: rows {i, i+512} x offsets d in {tid+1, tid+257}
//   with j = (row + d) mod 1024; covers every off-diagonal unordered pair
//   (distance-512 twice, bitwise-identical values). Writes out[i,j] and out[j,i].
// - threads 0..15 also write the two diagonal entries.
__global__ __launch_bounds__(256)
void relbias_kernel(const float* __restrict__ vec,  // [B, 1024, 3]
                    const float* __restrict__ W,    // [64, 16]
                    const float* __restrict__ bias, // [16]
                    float* __restrict__ out) {
    __shared__ __align__(16) float sW[2 * NF * NH]; // rows 0..31 sin, 32..63 cos
    __shared__ float sV[NPTS * 3];
    __shared__ float sB[NH];

    int tid = threadIdx.x;
    int b = blockIdx.y;
    int i0 = blockIdx.x;                  // first of the two rows

    for (int idx = tid; idx < 2 * NF * NH; idx += 256) sW[idx] = W[idx];
    if (tid < NH) sB[tid] = bias[tid];

    // fused normalize of the whole batch-row set
    const float* vb = vec + b * NPTS * 3;
    for (int v = tid; v < NPTS; v += 256) {
        float x = vb[v * 3 + 0];
        float y = vb[v * 3 + 1];
        float z = vb[v * 3 + 2];
        float rn = rsqrtf(x * x + y * y + z * z);
        sV[v * 3 + 0] = x * rn;
        sV[v * 3 + 1] = y * rn;
        sV[v * 3 + 2] = z * rn;
    }
    __syncthreads();

    long long bb = (long long)b * NPTS;

    // diagonal: angle = 0 -> out = bias + sum_k Wc[k,:]
    if (tid < NH) {
        float a = sB[tid];
#pragma unroll
        for (int k = 0; k < NF; ++k) a += sW[(NF + k) * NH + tid];
        out[((bb + i0) * NPTS + i0) * NH + tid] = a;
        out[((bb + i0 + 512) * NPTS + (i0 + 512)) * NH + tid] = a;
    }

    int rows[2] = { i0, i0 + 512 };
    float vr[2][3];
#pragma unroll
    for (int r = 0; r < 2; ++r) {
        vr[r][0] = sV[rows[r] * 3 + 0];
        vr[r][1] = sV[rows[r] * 3 + 1];
        vr[r][2] = sV[rows[r] * 3 + 2];
    }

    int jj[4];
    float s[4], c[4], s1[4], c1[4];
#pragma unroll
    for (int p = 0; p < 4; ++p) {
        int r = p >> 1;
        int d = 1 + tid + 256 * (p & 1);          // 1..512
        int j = (rows[r] + d) & (NPTS - 1);
        jj[p] = j;
        float dx = vr[r][0] - sV[j * 3 + 0];
        float dy = vr[r][1] - sV[j * 3 + 1];
        float dz = vr[r][2] - sV[j * 3 + 2];
        float dot = 1.0f - 0.5f * ((dx * dx + dy * dy) + dz * dz);
        dot = fminf(fmaxf(dot, -1.0f), 1.0f);
        float angle = acosf(dot) * 200.0f;        // / 0.005
        float t = angle * (10.0f / 31.0f);        // base phase step

        // fp32 Cody-Waite reduction mod 2*pi  (t <= ~203, q <= 33)
        float q = nearbyintf(t * 0.15915494309189535f);
        float tr = fmaf(q, -6.28125f, t);              // C1 exact in fp32
        tr = fmaf(q, -1.9353071795864769e-3f, tr);     // C2 = 2*pi - C1
        s1[p] = __sinf(tr);
        c1[p] = __cosf(tr);
        s[p] = 0.0f;   // sin(0*t)
        c[p] = 1.0f;   // cos(0*t)
    }

    // accumulators: 4 pairs x 8 packed f32x2 = 16 heads each, init with bias
    unsigned long long acc[4][8];
    {
        unsigned long long bv[8];
#pragma unroll
        for (int q = 0; q < 8; ++q) bv[q] = pack2(sB[2 * q], sB[2 * q + 1]);
#pragma unroll
        for (int p = 0; p < 4; ++p)
#pragma unroll
            for (int q = 0; q < 8; ++q) acc[p][q] = bv[q];
    }

    const ulonglong2* sWs2 = (const ulonglong2*)sW;             // 4 u2 per row
    const ulonglong2* sWc2 = (const ulonglong2*)(sW + NF * NH);

#pragma unroll 2
    for (int k = 0; k < NF; ++k) {
        // hoist the 8 weight vectors for this frequency; reuse across 4 pairs
        ulonglong2 a0 = sWs2[4 * k + 0];
        ulonglong2 a1 = sWs2[4 * k + 1];
        ulonglong2 a2 = sWs2[4 * k + 2];
        ulonglong2 a3 = sWs2[4 * k + 3];
        ulonglong2 w0 = sWc2[4 * k + 0];
        ulonglong2 w1 = sWc2[4 * k + 1];
        ulonglong2 w2 = sWc2[4 * k + 2];
        ulonglong2 w3 = sWc2[4 * k + 3];
#pragma unroll
        for (int p = 0; p < 4; ++p) {
            unsigned long long sp = pack_dup(s[p]);
            unsigned long long cp = pack_dup(c[p]);
            fma2(acc[p][0], sp, a0.x); fma2(acc[p][1], sp, a0.y);
            fma2(acc[p][2], sp, a1.x); fma2(acc[p][3], sp, a1.y);
            fma2(acc[p][4], sp, a2.x); fma2(acc[p][5], sp, a2.y);
            fma2(acc[p][6], sp, a3.x); fma2(acc[p][7], sp, a3.y);
            fma2(acc[p][0], cp, w0.x); fma2(acc[p][1], cp, w0.y);
            fma2(acc[p][2], cp, w1.x); fma2(acc[p][3], cp, w1.y);
            fma2(acc[p][4], cp, w2.x); fma2(acc[p][5], cp, w2.y);
            fma2(acc[p][6], cp, w3.x); fma2(acc[p][7], cp, w3.y);
            // rotate: (s, c) -> (s*c1 + c*s1, c*c1 - s*s1)
            float ns = fmaf(s[p], c1[p], c[p] * s1[p]);
            float nc = fmaf(c[p], c1[p], -(s[p] * s1[p]));
            s[p] = ns;
            c[p] = nc;
        }
    }

    // each pair writes out[b,i,j,:] and out[b,j,i,:] (16 floats each)
#pragma unroll
    for (int p = 0; p < 4; ++p) {
        int r = p >> 1;
        int i = rows[r];
        int j = jj[p];
        float4 v[4];
#pragma unroll
        for (int q = 0; q < 4; ++q) {
            float2 lo = unpack2(acc[p][2 * q]);
            float2 hi = unpack2(acc[p][2 * q + 1]);
            v[q] = make_float4(lo.x, lo.y, hi.x, hi.y);
        }
        float4* o_ij = (float4*)out + ((bb + i) * NPTS + j) * 4;
        float4* o_ji = (float4*)out + ((bb + j) * NPTS + i) * 4;
#pragma unroll
        for (int q = 0; q < 4; ++q) o_ij[q] = v[q];
#pragma unroll
        for (int q = 0; q < 4; ++q) o_ji[q] = v[q];
    }
}

extern "C" void kernel_launch(void* const* d_in, const int* in_sizes, int n_in,
                              void* d_out, int out_size) {
    const float* vec_map = (const float*)d_in[0];
    const float* kernelW = (const float*)d_in[1];
    const float* bias    = (const float*)d_in[2];
    float* out = (float*)d_out;

    int total_vecs = in_sizes[0] / 3;       // B * N
    int B = total_vecs / NPTS;

    dim3 grid(NPTS / 2, B);
    relbias_kernel<<<grid, 256>>>(vec_map, kernelW, bias, out);
}

// round 5
// speedup vs baseline: 1.6000x; 1.6000x over previous
#include <cuda_runtime.h>
#include <math.h>

#define NPTS 1024
#define NF   32     // frequency pairs (sin+cos => 64 features)
#define NH   16     // heads

// ---- packed f32x2 helpers (Blackwell FFMA2 path) ----
__device__ __forceinline__ unsigned long long pack_dup(float x) {
    unsigned long long r;
    asm("mov.b64 %0, {%1, %1};" : "=l"(r) : "f"(x));
    return r;
}
__device__ __forceinline__ unsigned long long pack2(float lo, float hi) {
    unsigned long long r;
    asm("mov.b64 %0, {%1, %2};" : "=l"(r) : "f"(lo), "f"(hi));
    return r;
}
__device__ __forceinline__ void fma2(unsigned long long& d,
                                     unsigned long long a,
                                     unsigned long long b) {
    asm("fma.rn.f32x2 %0, %1, %2, %0;" : "+l"(d) : "l"(a), "l"(b));
}
__device__ __forceinline__ float2 unpack2(unsigned long long v) {
    float lo, hi;
    asm("mov.b64 {%0, %1}, %2;" : "=f"(lo), "=f"(hi) : "l"(v));
    return make_float2(lo, hi);
}

// Fully fused kernel. Block = rows (i, i+512) of batch b.
// - cooperatively normalizes all 1024 vectors of batch b into SMEM
// - thread tid handles 4 pairs: rows {i, i+512} x offsets d in {tid+1, tid+257}
//   with j = (row + d) mod 1024; covers every off-diagonal unordered pair
//   (distance-512 twice, bitwise-identical values). Writes out[i,j] and out[j,i].
// - threads 0..15 also write the two diagonal entries.
__global__ __launch_bounds__(256)
void relbias_kernel(const float* __restrict__ vec,  // [B, 1024, 3]
                    const float* __restrict__ W,    // [64, 16]
                    const float* __restrict__ bias, // [16]
                    float* __restrict__ out) {
    __shared__ __align__(16) float sW[2 * NF * NH]; // rows 0..31 sin, 32..63 cos
    __shared__ float sV[NPTS * 3];
    __shared__ float sB[NH];

    int tid = threadIdx.x;
    int b = blockIdx.y;
    int i0 = blockIdx.x;                  // first of the two rows

    for (int idx = tid; idx < 2 * NF * NH; idx += 256) sW[idx] = W[idx];
    if (tid < NH) sB[tid] = bias[tid];

    // fused normalize of the whole batch-row set
    const float* vb = vec + b * NPTS * 3;
    for (int v = tid; v < NPTS; v += 256) {
        float x = vb[v * 3 + 0];
        float y = vb[v * 3 + 1];
        float z = vb[v * 3 + 2];
        float rn = rsqrtf(x * x + y * y + z * z);
        sV[v * 3 + 0] = x * rn;
        sV[v * 3 + 1] = y * rn;
        sV[v * 3 + 2] = z * rn;
    }
    __syncthreads();

    long long bb = (long long)b * NPTS;

    // diagonal: angle = 0 -> out = bias + sum_k Wc[k,:]
    if (tid < NH) {
        float a = sB[tid];
#pragma unroll
        for (int k = 0; k < NF; ++k) a += sW[(NF + k) * NH + tid];
        out[((bb + i0) * NPTS + i0) * NH + tid] = a;
        out[((bb + i0 + 512) * NPTS + (i0 + 512)) * NH + tid] = a;
    }

    int rows[2] = { i0, i0 + 512 };
    float vr[2][3];
#pragma unroll
    for (int r = 0; r < 2; ++r) {
        vr[r][0] = sV[rows[r] * 3 + 0];
        vr[r][1] = sV[rows[r] * 3 + 1];
        vr[r][2] = sV[rows[r] * 3 + 2];
    }

    int jj[4];
    float s[4], c[4], s1[4], c1[4];
#pragma unroll
    for (int p = 0; p < 4; ++p) {
        int r = p >> 1;
        int d = 1 + tid + 256 * (p & 1);          // 1..512
        int j = (rows[r] + d) & (NPTS - 1);
        jj[p] = j;
        float dx = vr[r][0] - sV[j * 3 + 0];
        float dy = vr[r][1] - sV[j * 3 + 1];
        float dz = vr[r][2] - sV[j * 3 + 2];
        float dot = 1.0f - 0.5f * ((dx * dx + dy * dy) + dz * dz);
        dot = fminf(fmaxf(dot, -1.0f), 1.0f);
        float angle = acosf(dot) * 200.0f;        // / 0.005
        float t = angle * (10.0f / 31.0f);        // base phase step

        // fp32 Cody-Waite reduction mod 2*pi  (t <= ~203, q <= 33)
        float q = nearbyintf(t * 0.15915494309189535f);
        float tr = fmaf(q, -6.28125f, t);              // C1 exact in fp32
        tr = fmaf(q, -1.9353071795864769e-3f, tr);     // C2 = 2*pi - C1
        s1[p] = __sinf(tr);
        c1[p] = __cosf(tr);
        s[p] = 0.0f;   // sin(0*t)
        c[p] = 1.0f;   // cos(0*t)
    }

    // accumulators: 4 pairs x 8 packed f32x2 = 16 heads each, init with bias
    unsigned long long acc[4][8];
    {
        unsigned long long bv[8];
#pragma unroll
        for (int q = 0; q < 8; ++q) bv[q] = pack2(sB[2 * q], sB[2 * q + 1]);
#pragma unroll
        for (int p = 0; p < 4; ++p)
#pragma unroll
            for (int q = 0; q < 8; ++q) acc[p][q] = bv[q];
    }

    const ulonglong2* sWs2 = (const ulonglong2*)sW;             // 4 u2 per row
    const ulonglong2* sWc2 = (const ulonglong2*)(sW + NF * NH);

#pragma unroll 2
    for (int k = 0; k < NF; ++k) {
        // hoist the 8 weight vectors for this frequency; reuse across 4 pairs
        ulonglong2 a0 = sWs2[4 * k + 0];
        ulonglong2 a1 = sWs2[4 * k + 1];
        ulonglong2 a2 = sWs2[4 * k + 2];
        ulonglong2 a3 = sWs2[4 * k + 3];
        ulonglong2 w0 = sWc2[4 * k + 0];
        ulonglong2 w1 = sWc2[4 * k + 1];
        ulonglong2 w2 = sWc2[4 * k + 2];
        ulonglong2 w3 = sWc2[4 * k + 3];
#pragma unroll
        for (int p = 0; p < 4; ++p) {
            unsigned long long sp = pack_dup(s[p]);
            unsigned long long cp = pack_dup(c[p]);
            fma2(acc[p][0], sp, a0.x); fma2(acc[p][1], sp, a0.y);
            fma2(acc[p][2], sp, a1.x); fma2(acc[p][3], sp, a1.y);
            fma2(acc[p][4], sp, a2.x); fma2(acc[p][5], sp, a2.y);
            fma2(acc[p][6], sp, a3.x); fma2(acc[p][7], sp, a3.y);
            fma2(acc[p][0], cp, w0.x); fma2(acc[p][1], cp, w0.y);
            fma2(acc[p][2], cp, w1.x); fma2(acc[p][3], cp, w1.y);
            fma2(acc[p][4], cp, w2.x); fma2(acc[p][5], cp, w2.y);
            fma2(acc[p][6], cp, w3.x); fma2(acc[p][7], cp, w3.y);
            // rotate: (s, c) -> (s*c1 + c*s1, c*c1 - s*s1)
            float ns = fmaf(s[p], c1[p], c[p] * s1[p]);
            float nc = fmaf(c[p], c1[p], -(s[p] * s1[p]));
            s[p] = ns;
            c[p] = nc;
        }
    }

    // each pair writes out[b,i,j,:] and out[b,j,i,:] (16 floats each)
#pragma unroll
    for (int p = 0; p < 4; ++p) {
        int r = p >> 1;
        int i = rows[r];
        int j = jj[p];
        float4 v[4];
#pragma unroll
        for (int q = 0; q < 4; ++q) {
            float2 lo = unpack2(acc[p][2 * q]);
            float2 hi = unpack2(acc[p][2 * q + 1]);
            v[q] = make_float4(lo.x, lo.y, hi.x, hi.y);
        }
        float4* o_ij = (float4*)out + ((bb + i) * NPTS + j) * 4;
        float4* o_ji = (float4*)out + ((bb + j) * NPTS + i) * 4;
#pragma unroll
        for (int q = 0; q < 4; ++q) o_ij[q] = v[q];
#pragma unroll
        for (int q = 0; q < 4; ++q) o_ji[q] = v[q];
    }
}

extern "C" void kernel_launch(void* const* d_in, const int* in_sizes, int n_in,
                              void* d_out, int out_size) {
    const float* vec_map = (const float*)d_in[0];
    const float* kernelW = (const float*)d_in[1];
    const float* bias    = (const float*)d_in[2];
    float* out = (float*)d_out;

    int total_vecs = in_sizes[0] / 3;       // B * N
    int B = total_vecs / NPTS;

    dim3 grid(NPTS / 2, B);
    relbias_kernel<<<grid, 256>>>(vec_map, kernelW, bias, out);
}

// round 6
// speedup vs baseline: 1.6116x; 1.0073x over previous
#include <cuda_runtime.h>
#include <math.h>

#define NPTS 1024
#define NF   32     // frequency pairs (sin+cos => 64 features)
#define NH   16     // heads

// ---- packed f32x2 helpers (Blackwell FFMA2 path) ----
__device__ __forceinline__ unsigned long long pack_dup(float x) {
    unsigned long long r;
    asm("mov.b64 %0, {%1, %1};" : "=l"(r) : "f"(x));
    return r;
}
__device__ __forceinline__ unsigned long long pack2(float lo, float hi) {
    unsigned long long r;
    asm("mov.b64 %0, {%1, %2};" : "=l"(r) : "f"(lo), "f"(hi));
    return r;
}
__device__ __forceinline__ void fma2(unsigned long long& d,
                                     unsigned long long a,
                                     unsigned long long b) {
    asm("fma.rn.f32x2 %0, %1, %2, %0;" : "+l"(d) : "l"(a), "l"(b));
}
__device__ __forceinline__ float2 unpack2(unsigned long long v) {
    float lo, hi;
    asm("mov.b64 {%0, %1}, %2;" : "=f"(lo), "=f"(hi) : "l"(v));
    return make_float2(lo, hi);
}

// Fully fused kernel. Block = rows (i, i+512) of batch b.
// - cooperatively normalizes all 1024 vectors of batch b into SMEM
// - thread tid handles 4 pairs: rows {i, i+512} x offsets d in {tid+1, tid+257}
//   with j = (row + d) mod 1024; covers every off-diagonal unordered pair
//   (distance-512 twice, bitwise-identical values). Writes out[i,j] and out[j,i].
// - threads 0..15 also write the two diagonal entries.
__global__ __launch_bounds__(256)
void relbias_kernel(const float* __restrict__ vec,  // [B, 1024, 3]
                    const float* __restrict__ W,    // [64, 16]
                    const float* __restrict__ bias, // [16]
                    float* __restrict__ out) {
    __shared__ __align__(16) float sW[2 * NF * NH]; // rows 0..31 sin, 32..63 cos
    __shared__ float sV[NPTS * 3];
    __shared__ float sB[NH];

    int tid = threadIdx.x;
    int b = blockIdx.y;
    int i0 = blockIdx.x;                  // first of the two rows

    for (int idx = tid; idx < 2 * NF * NH; idx += 256) sW[idx] = W[idx];
    if (tid < NH) sB[tid] = bias[tid];

    // fused normalize of the whole batch-row set
    const float* vb = vec + b * NPTS * 3;
    for (int v = tid; v < NPTS; v += 256) {
        float x = vb[v * 3 + 0];
        float y = vb[v * 3 + 1];
        float z = vb[v * 3 + 2];
        float rn = rsqrtf(x * x + y * y + z * z);
        sV[v * 3 + 0] = x * rn;
        sV[v * 3 + 1] = y * rn;
        sV[v * 3 + 2] = z * rn;
    }
    __syncthreads();

    long long bb = (long long)b * NPTS;

    // diagonal: angle = 0 -> out = bias + sum_k Wc[k,:]
    if (tid < NH) {
        float a = sB[tid];
#pragma unroll
        for (int k = 0; k < NF; ++k) a += sW[(NF + k) * NH + tid];
        out[((bb + i0) * NPTS + i0) * NH + tid] = a;
        out[((bb + i0 + 512) * NPTS + (i0 + 512)) * NH + tid] = a;
    }

    int rows[2] = { i0, i0 + 512 };
    float vr[2][3];
#pragma unroll
    for (int r = 0; r < 2; ++r) {
        vr[r][0] = sV[rows[r] * 3 + 0];
        vr[r][1] = sV[rows[r] * 3 + 1];
        vr[r][2] = sV[rows[r] * 3 + 2];
    }

    int jj[4];
    float s[4], c[4], s1[4], c1[4];
#pragma unroll
    for (int p = 0; p < 4; ++p) {
        int r = p >> 1;
        int d = 1 + tid + 256 * (p & 1);          // 1..512
        int j = (rows[r] + d) & (NPTS - 1);
        jj[p] = j;
        float dx = vr[r][0] - sV[j * 3 + 0];
        float dy = vr[r][1] - sV[j * 3 + 1];
        float dz = vr[r][2] - sV[j * 3 + 2];
        float dot = 1.0f - 0.5f * ((dx * dx + dy * dy) + dz * dz);
        dot = fminf(fmaxf(dot, -1.0f), 1.0f);
        float angle = acosf(dot) * 200.0f;        // / 0.005
        float t = angle * (10.0f / 31.0f);        // base phase step

        // fp32 Cody-Waite reduction mod 2*pi  (t <= ~203, q <= 33)
        float q = nearbyintf(t * 0.15915494309189535f);
        float tr = fmaf(q, -6.28125f, t);              // C1 exact in fp32
        tr = fmaf(q, -1.9353071795864769e-3f, tr);     // C2 = 2*pi - C1
        s1[p] = __sinf(tr);
        c1[p] = __cosf(tr);
        s[p] = 0.0f;   // sin(0*t)
        c[p] = 1.0f;   // cos(0*t)
    }

    // accumulators: 4 pairs x 8 packed f32x2 = 16 heads each, init with bias
    unsigned long long acc[4][8];
    {
        unsigned long long bv[8];
#pragma unroll
        for (int q = 0; q < 8; ++q) bv[q] = pack2(sB[2 * q], sB[2 * q + 1]);
#pragma unroll
        for (int p = 0; p < 4; ++p)
#pragma unroll
            for (int q = 0; q < 8; ++q) acc[p][q] = bv[q];
    }

    const ulonglong2* sWs2 = (const ulonglong2*)sW;             // 4 u2 per row
    const ulonglong2* sWc2 = (const ulonglong2*)(sW + NF * NH);

#pragma unroll 2
    for (int k = 0; k < NF; ++k) {
        // hoist the 8 weight vectors for this frequency; reuse across 4 pairs
        ulonglong2 a0 = sWs2[4 * k + 0];
        ulonglong2 a1 = sWs2[4 * k + 1];
        ulonglong2 a2 = sWs2[4 * k + 2];
        ulonglong2 a3 = sWs2[4 * k + 3];
        ulonglong2 w0 = sWc2[4 * k + 0];
        ulonglong2 w1 = sWc2[4 * k + 1];
        ulonglong2 w2 = sWc2[4 * k + 2];
        ulonglong2 w3 = sWc2[4 * k + 3];
#pragma unroll
        for (int p = 0; p < 4; ++p) {
            unsigned long long sp = pack_dup(s[p]);
            unsigned long long cp = pack_dup(c[p]);
            fma2(acc[p][0], sp, a0.x); fma2(acc[p][1], sp, a0.y);
            fma2(acc[p][2], sp, a1.x); fma2(acc[p][3], sp, a1.y);
            fma2(acc[p][4], sp, a2.x); fma2(acc[p][5], sp, a2.y);
            fma2(acc[p][6], sp, a3.x); fma2(acc[p][7], sp, a3.y);
            fma2(acc[p][0], cp, w0.x); fma2(acc[p][1], cp, w0.y);
            fma2(acc[p][2], cp, w1.x); fma2(acc[p][3], cp, w1.y);
            fma2(acc[p][4], cp, w2.x); fma2(acc[p][5], cp, w2.y);
            fma2(acc[p][6], cp, w3.x); fma2(acc[p][7], cp, w3.y);
            // rotate: (s, c) -> (s*c1 + c*s1, c*c1 - s*s1)
            float ns = fmaf(s[p], c1[p], c[p] * s1[p]);
            float nc = fmaf(c[p], c1[p], -(s[p] * s1[p]));
            s[p] = ns;
            c[p] = nc;
        }
    }

    // each pair writes out[b,i,j,:] and out[b,j,i,:] (16 floats each)
#pragma unroll
    for (int p = 0; p < 4; ++p) {
        int r = p >> 1;
        int i = rows[r];
        int j = jj[p];
        float4 v[4];
#pragma unroll
        for (int q = 0; q < 4; ++q) {
            float2 lo = unpack2(acc[p][2 * q]);
            float2 hi = unpack2(acc[p][2 * q + 1]);
            v[q] = make_float4(lo.x, lo.y, hi.x, hi.y);
        }
        float4* o_ij = (float4*)out + ((bb + i) * NPTS + j) * 4;
        float4* o_ji = (float4*)out + ((bb + j) * NPTS + i) * 4;
#pragma unroll
        for (int q = 0; q < 4; ++q) o_ij[q] = v[q];
#pragma unroll
        for (int q = 0; q < 4; ++q) o_ji[q] = v[q];
    }
}

extern "C" void kernel_launch(void* const* d_in, const int* in_sizes, int n_in,
                              void* d_out, int out_size) {
    const float* vec_map = (const float*)d_in[0];
    const float* kernelW = (const float*)d_in[1];
    const float* bias    = (const float*)d_in[2];
    float* out = (float*)d_out;

    int total_vecs = in_sizes[0] / 3;       // B * N
    int B = total_vecs / NPTS;

    dim3 grid(NPTS / 2, B);
    relbias_kernel<<<grid, 256>>>(vec_map, kernelW, bias, out);
}

// round 7
// speedup vs baseline: 1.6175x; 1.0037x over previous
#include <cuda_runtime.h>
#include <math.h>

#define NPTS 1024
#define NF   32     // frequency pairs (sin+cos => 64 features)
#define NH   16     // heads

// ---- packed f32x2 helpers (Blackwell FFMA2 path) ----
__device__ __forceinline__ unsigned long long pack_dup(float x) {
    unsigned long long r;
    asm("mov.b64 %0, {%1, %1};" : "=l"(r) : "f"(x));
    return r;
}
__device__ __forceinline__ unsigned long long pack2(float lo, float hi) {
    unsigned long long r;
    asm("mov.b64 %0, {%1, %2};" : "=l"(r) : "f"(lo), "f"(hi));
    return r;
}
__device__ __forceinline__ void fma2(unsigned long long& d,
                                     unsigned long long a,
                                     unsigned long long b) {
    asm("fma.rn.f32x2 %0, %1, %2, %0;" : "+l"(d) : "l"(a), "l"(b));
}
__device__ __forceinline__ float2 unpack2(unsigned long long v) {
    float lo, hi;
    asm("mov.b64 {%0, %1}, %2;" : "=f"(lo), "=f"(hi) : "l"(v));
    return make_float2(lo, hi);
}

// Fully fused kernel. Block = rows (i, i+512) of batch b.
// - cooperatively normalizes all 1024 vectors of batch b into SMEM
// - thread tid handles 4 pairs: rows {i, i+512} x offsets d in {tid+1, tid+257}
//   with j = (row + d) mod 1024; covers every off-diagonal unordered pair
//   (distance-512 twice, bitwise-identical values). Writes out[i,j] and out[j,i].
// - threads 0..15 also write the two diagonal entries.
__global__ __launch_bounds__(256)
void relbias_kernel(const float* __restrict__ vec,  // [B, 1024, 3]
                    const float* __restrict__ W,    // [64, 16]
                    const float* __restrict__ bias, // [16]
                    float* __restrict__ out) {
    __shared__ __align__(16) float sW[2 * NF * NH]; // rows 0..31 sin, 32..63 cos
    __shared__ float sV[NPTS * 3];
    __shared__ float sB[NH];

    int tid = threadIdx.x;
    int b = blockIdx.y;
    int i0 = blockIdx.x;                  // first of the two rows

    for (int idx = tid; idx < 2 * NF * NH; idx += 256) sW[idx] = W[idx];
    if (tid < NH) sB[tid] = bias[tid];

    // fused normalize of the whole batch-row set
    const float* vb = vec + b * NPTS * 3;
    for (int v = tid; v < NPTS; v += 256) {
        float x = vb[v * 3 + 0];
        float y = vb[v * 3 + 1];
        float z = vb[v * 3 + 2];
        float rn = rsqrtf(x * x + y * y + z * z);
        sV[v * 3 + 0] = x * rn;
        sV[v * 3 + 1] = y * rn;
        sV[v * 3 + 2] = z * rn;
    }
    __syncthreads();

    long long bb = (long long)b * NPTS;

    // diagonal: angle = 0 -> out = bias + sum_k Wc[k,:]
    if (tid < NH) {
        float a = sB[tid];
#pragma unroll
        for (int k = 0; k < NF; ++k) a += sW[(NF + k) * NH + tid];
        out[((bb + i0) * NPTS + i0) * NH + tid] = a;
        out[((bb + i0 + 512) * NPTS + (i0 + 512)) * NH + tid] = a;
    }

    int rows[2] = { i0, i0 + 512 };
    float vr[2][3];
#pragma unroll
    for (int r = 0; r < 2; ++r) {
        vr[r][0] = sV[rows[r] * 3 + 0];
        vr[r][1] = sV[rows[r] * 3 + 1];
        vr[r][2] = sV[rows[r] * 3 + 2];
    }

    int jj[4];
    float s[4], c[4], s1[4], c1[4];
#pragma unroll
    for (int p = 0; p < 4; ++p) {
        int r = p >> 1;
        int d = 1 + tid + 256 * (p & 1);          // 1..512
        int j = (rows[r] + d) & (NPTS - 1);
        jj[p] = j;
        float dx = vr[r][0] - sV[j * 3 + 0];
        float dy = vr[r][1] - sV[j * 3 + 1];
        float dz = vr[r][2] - sV[j * 3 + 2];
        float dot = 1.0f - 0.5f * ((dx * dx + dy * dy) + dz * dz);
        dot = fminf(fmaxf(dot, -1.0f), 1.0f);
        float angle = acosf(dot) * 200.0f;        // / 0.005
        float t = angle * (10.0f / 31.0f);        // base phase step

        // fp32 Cody-Waite reduction mod 2*pi  (t <= ~203, q <= 33)
        float q = nearbyintf(t * 0.15915494309189535f);
        float tr = fmaf(q, -6.28125f, t);              // C1 exact in fp32
        tr = fmaf(q, -1.9353071795864769e-3f, tr);     // C2 = 2*pi - C1
        s1[p] = __sinf(tr);
        c1[p] = __cosf(tr);
        s[p] = 0.0f;   // sin(0*t)
        c[p] = 1.0f;   // cos(0*t)
    }

    // accumulators: 4 pairs x 8 packed f32x2 = 16 heads each, init with bias
    unsigned long long acc[4][8];
    {
        unsigned long long bv[8];
#pragma unroll
        for (int q = 0; q < 8; ++q) bv[q] = pack2(sB[2 * q], sB[2 * q + 1]);
#pragma unroll
        for (int p = 0; p < 4; ++p)
#pragma unroll
            for (int q = 0; q < 8; ++q) acc[p][q] = bv[q];
    }

    const ulonglong2* sWs2 = (const ulonglong2*)sW;             // 4 u2 per row
    const ulonglong2* sWc2 = (const ulonglong2*)(sW + NF * NH);

#pragma unroll 2
    for (int k = 0; k < NF; ++k) {
        // hoist the 8 weight vectors for this frequency; reuse across 4 pairs
        ulonglong2 a0 = sWs2[4 * k + 0];
        ulonglong2 a1 = sWs2[4 * k + 1];
        ulonglong2 a2 = sWs2[4 * k + 2];
        ulonglong2 a3 = sWs2[4 * k + 3];
        ulonglong2 w0 = sWc2[4 * k + 0];
        ulonglong2 w1 = sWc2[4 * k + 1];
        ulonglong2 w2 = sWc2[4 * k + 2];
        ulonglong2 w3 = sWc2[4 * k + 3];
#pragma unroll
        for (int p = 0; p < 4; ++p) {
            unsigned long long sp = pack_dup(s[p]);
            unsigned long long cp = pack_dup(c[p]);
            fma2(acc[p][0], sp, a0.x); fma2(acc[p][1], sp, a0.y);
            fma2(acc[p][2], sp, a1.x); fma2(acc[p][3], sp, a1.y);
            fma2(acc[p][4], sp, a2.x); fma2(acc[p][5], sp, a2.y);
            fma2(acc[p][6], sp, a3.x); fma2(acc[p][7], sp, a3.y);
            fma2(acc[p][0], cp, w0.x); fma2(acc[p][1], cp, w0.y);
            fma2(acc[p][2], cp, w1.x); fma2(acc[p][3], cp, w1.y);
            fma2(acc[p][4], cp, w2.x); fma2(acc[p][5], cp, w2.y);
            fma2(acc[p][6], cp, w3.x); fma2(acc[p][7], cp, w3.y);
            // rotate: (s, c) -> (s*c1 + c*s1, c*c1 - s*s1)
            float ns = fmaf(s[p], c1[p], c[p] * s1[p]);
            float nc = fmaf(c[p], c1[p], -(s[p] * s1[p]));
            s[p] = ns;
            c[p] = nc;
        }
    }

    // each pair writes out[b,i,j,:] and out[b,j,i,:] (16 floats each)
#pragma unroll
    for (int p = 0; p < 4; ++p) {
        int r = p >> 1;
        int i = rows[r];
        int j = jj[p];
        float4 v[4];
#pragma unroll
        for (int q = 0; q < 4; ++q) {
            float2 lo = unpack2(acc[p][2 * q]);
            float2 hi = unpack2(acc[p][2 * q + 1]);
            v[q] = make_float4(lo.x, lo.y, hi.x, hi.y);
        }
        float4* o_ij = (float4*)out + ((bb + i) * NPTS + j) * 4;
        float4* o_ji = (float4*)out + ((bb + j) * NPTS + i) * 4;
#pragma unroll
        for (int q = 0; q < 4; ++q) o_ij[q] = v[q];
#pragma unroll
        for (int q = 0; q < 4; ++q) o_ji[q] = v[q];
    }
}

extern "C" void kernel_launch(void* const* d_in, const int* in_sizes, int n_in,
                              void* d_out, int out_size) {
    const float* vec_map = (const float*)d_in[0];
    const float* kernelW = (const float*)d_in[1];
    const float* bias    = (const float*)d_in[2];
    float* out = (float*)d_out;

    int total_vecs = in_sizes[0] / 3;       // B * N
    int B = total_vecs / NPTS;

    dim3 grid(NPTS / 2, B);
    relbias_kernel<<<grid, 256>>>(vec_map, kernelW, bias, out);
}

// round 9
// speedup vs baseline: 2.7178x; 1.6802x over previous
#include <cuda_runtime.h>
#include <cuda_fp16.h>
#include <math.h>
#include <stdint.h>

#define NPTS 1024
#define NH   16
#define ASTRIDE 144   // bytes per SMEM tile row: 64 fp16 = 128B + 16B pad (conflict-free)

static __device__ __forceinline__ uint32_t smem_addr(const void* p) {
    return (uint32_t)__cvta_generic_to_shared(p);
}

static __device__ __forceinline__ void ldsm_x4(uint32_t& r0, uint32_t& r1,
                                               uint32_t& r2, uint32_t& r3, uint32_t a) {
    asm volatile("ldmatrix.sync.aligned.m8n8.x4.shared.b16 {%0,%1,%2,%3}, [%4];"
                 : "=r"(r0), "=r"(r1), "=r"(r2), "=r"(r3) : "r"(a));
}

static __device__ __forceinline__ void mma16816(float& d0, float& d1, float& d2, float& d3,
                                                uint32_t a0, uint32_t a1, uint32_t a2, uint32_t a3,
                                                uint32_t b0, uint32_t b1) {
    asm volatile("mma.sync.aligned.m16n8k16.row.col.f32.f16.f16.f32 "
                 "{%0,%1,%2,%3}, {%4,%5,%6,%7}, {%8,%9}, {%0,%1,%2,%3};"
                 : "+f"(d0), "+f"(d1), "+f"(d2), "+f"(d3)
                 : "r"(a0), "r"(a1), "r"(a2), "r"(a3), "r"(b0), "r"(b1));
}

// Fused kernel. grid = (1024 rows i, 4 d-blocks, B); block = 128 threads.
// Thread tid generates features for pair (i, j), j = (i + dbase + tid + 1) mod 1024,
// into SMEM row tid. Then 4 warps run HMMA: D[128 pairs, 16 heads] = P[128,64] @ Wt[64,16].
// Covers every off-diagonal unordered pair once (distance-512 twice, bitwise identical);
// writes out[i,j,:] and out[j,i,:]. Diagonal written by d-block 0.
__global__ __launch_bounds__(128)
void relbias_kernel(const float* __restrict__ vec,  // [B,1024,3]
                    const float* __restrict__ W,    // [64,16]
                    const float* __restrict__ bias, // [16]
                    float* __restrict__ out) {
    __shared__ __align__(16) uint8_t sA[128 * ASTRIDE];  // fp16 features, row = pair
    __shared__ __align__(16) uint8_t sW[16 * ASTRIDE];   // fp16 weights [n][f']

    int tid = threadIdx.x;
    int i     = blockIdx.x;
    int dbase = blockIdx.y << 7;
    int b     = blockIdx.z;

    // W[64,16] fp32 -> sW[n][f'] fp16, f' interleaved: f'=2k -> Ws[k], f'=2k+1 -> Wc[k]
    for (int idx = tid; idx < 64 * 16; idx += 128) {
        int n = idx & 15, k = idx >> 4;
        int fp = (k < 32) ? (2 * k) : (2 * (k - 32) + 1);
        *(__half*)(sW + n * ASTRIDE + fp * 2) = __float2half_rn(W[idx]);
    }

    // ---- per-thread pair: angle + fp16 feature generation into SMEM row tid ----
    int d = dbase + tid + 1;                  // 1..512
    int j = (i + d) & (NPTS - 1);
    const float* vb = vec + (size_t)b * NPTS * 3;
    float ax = vb[i * 3 + 0], ay = vb[i * 3 + 1], az = vb[i * 3 + 2];
    float bx = vb[j * 3 + 0], by = vb[j * 3 + 1], bz = vb[j * 3 + 2];
    float ra = rsqrtf(ax * ax + ay * ay + az * az);
    float rb = rsqrtf(bx * bx + by * by + bz * bz);
    float dx = ax * ra - bx * rb;
    float dy = ay * ra - by * rb;
    float dz = az * ra - bz * rb;
    float dot = 1.0f - 0.5f * ((dx * dx + dy * dy) + dz * dz);
    dot = fminf(fmaxf(dot, -1.0f), 1.0f);
    float t = acosf(dot) * 200.0f * (10.0f / 31.0f);

    // fp32 Cody-Waite mod 2*pi
    float q  = nearbyintf(t * 0.15915494309189535f);
    float tr = fmaf(q, -6.28125f, t);
    tr = fmaf(q, -1.9353071795864769e-3f, tr);
    float s1 = __sinf(tr), c1 = __cosf(tr);
    // mid-chain anchor at k=16
    float t16 = 16.0f * tr;
    float q2  = nearbyintf(t16 * 0.15915494309189535f);
    float tr16 = fmaf(q2, -6.28125f, t16);
    tr16 = fmaf(q2, -1.9353071795864769e-3f, tr16);
    float s16 = __sinf(tr16), c16 = __cosf(tr16);

    {
        float s = 0.0f, c = 1.0f;
        uint32_t buf[4];
#pragma unroll
        for (int k = 0; k < 32; ++k) {
            __half2 h2 = __floats2half2_rn(s, c);    // low = sin (f'=2k), high = cos (f'=2k+1)
            buf[k & 3] = *reinterpret_cast<uint32_t*>(&h2);
            if ((k & 3) == 3) {
                *(uint4*)(sA + tid * ASTRIDE + (k >> 2) * 16) =
                    make_uint4(buf[0], buf[1], buf[2], buf[3]);
            }
            float ns = fmaf(s, c1, c * s1);
            float nc = fmaf(c, c1, -(s * s1));
            s = ns; c = nc;
            if (k == 15) { s = s16; c = c16; }       // re-anchor, halves drift
        }
    }

    // diagonal (exact fp32): out[b,i,i,:] = bias + sum_k Wc[k,:]
    long long bb = (long long)b * NPTS;
    if (blockIdx.y == 0 && tid < NH) {
        float a = bias[tid];
#pragma unroll
        for (int k = 0; k < 32; ++k) a += W[(32 + k) * NH + tid];
        out[((bb + i) * NPTS + i) * NH + tid] = a;
    }

    __syncthreads();

    // ---- HMMA: each warp computes 32 pairs x 16 heads ----
    int wid = tid >> 5, lane = tid & 31;
    int wbase = wid << 5;

    // B fragments: bfrag[ntile][ktile][2]
    uint32_t bfrag[2][4][2];
    uint32_t sWb = smem_addr(sW);
#pragma unroll
    for (int nt = 0; nt < 2; ++nt) {
#pragma unroll
        for (int ktp = 0; ktp < 2; ++ktp) {
            uint32_t a = sWb + (uint32_t)(nt * 8 + (lane & 7)) * ASTRIDE
                       + (uint32_t)ktp * 64 + (uint32_t)(lane >> 3) * 16;
            ldsm_x4(bfrag[nt][2 * ktp][0], bfrag[nt][2 * ktp][1],
                    bfrag[nt][2 * ktp + 1][0], bfrag[nt][2 * ktp + 1][1], a);
        }
    }

    float acc[2][2][4];
#pragma unroll
    for (int mt = 0; mt < 2; ++mt)
#pragma unroll
        for (int nt = 0; nt < 2; ++nt)
#pragma unroll
            for (int e = 0; e < 4; ++e) acc[mt][nt][e] = 0.0f;

    uint32_t sAb = smem_addr(sA);
#pragma unroll
    for (int mt = 0; mt < 2; ++mt) {
#pragma unroll
        for (int kt = 0; kt < 4; ++kt) {
            uint32_t a = sAb + (uint32_t)(wbase + mt * 16 + (lane & 15)) * ASTRIDE
                       + (uint32_t)kt * 32 + (uint32_t)(lane >> 4) * 16;
            uint32_t a0, a1, a2, a3;
            ldsm_x4(a0, a1, a2, a3, a);
#pragma unroll
            for (int nt = 0; nt < 2; ++nt)
                mma16816(acc[mt][nt][0], acc[mt][nt][1], acc[mt][nt][2], acc[mt][nt][3],
                         a0, a1, a2, a3, bfrag[nt][kt][0], bfrag[nt][kt][1]);
        }
    }

    // ---- epilogue: bias + symmetric stores ----
#pragma unroll
    for (int nt = 0; nt < 2; ++nt) {
        int col = nt * 8 + 2 * (lane & 3);
        float2 bz2 = *(const float2*)(bias + col);
#pragma unroll
        for (int mt = 0; mt < 2; ++mt) {
            int p_lo = wbase + mt * 16 + (lane >> 2);
            int p_hi = p_lo + 8;
            int j_lo = (i + dbase + p_lo + 1) & (NPTS - 1);
            int j_hi = (i + dbase + p_hi + 1) & (NPTS - 1);
            float2 vlo = make_float2(acc[mt][nt][0] + bz2.x, acc[mt][nt][1] + bz2.y);
            float2 vhi = make_float2(acc[mt][nt][2] + bz2.x, acc[mt][nt][3] + bz2.y);
            float* o;
            o = out + ((bb + i) * NPTS + j_lo) * NH + col;  *(float2*)o = vlo;
            o = out + ((bb + j_lo) * NPTS + i) * NH + col;  *(float2*)o = vlo;
            o = out + ((bb + i) * NPTS + j_hi) * NH + col;  *(float2*)o = vhi;
            o = out + ((bb + j_hi) * NPTS + i) * NH + col;  *(float2*)o = vhi;
        }
    }
}

extern "C" void kernel_launch(void* const* d_in, const int* in_sizes, int n_in,
                              void* d_out, int out_size) {
    const float* vec_map = (const float*)d_in[0];
    const float* kernelW = (const float*)d_in[1];
    const float* bias    = (const float*)d_in[2];
    float* out = (float*)d_out;

    int total_vecs = in_sizes[0] / 3;   // B * N
    int B = total_vecs / NPTS;

    dim3 grid(NPTS, 4, B);
    relbias_kernel<<<grid, 128>>>(vec_map, kernelW, bias, out);
}

// round 10
// speedup vs baseline: 3.4077x; 1.2538x over previous
#include <cuda_runtime.h>
#include <cuda_fp16.h>
#include <math.h>
#include <stdint.h>

#define NPTS 1024
#define NH   16
#define ASTRIDE 144   // bytes per SMEM tile row: 64 fp16 = 128B + 16B pad (conflict-free)
#define TPB  256

static __device__ __forceinline__ uint32_t smem_addr(const void* p) {
    return (uint32_t)__cvta_generic_to_shared(p);
}

static __device__ __forceinline__ void ldsm_x4(uint32_t& r0, uint32_t& r1,
                                               uint32_t& r2, uint32_t& r3, uint32_t a) {
    asm volatile("ldmatrix.sync.aligned.m8n8.x4.shared.b16 {%0,%1,%2,%3}, [%4];"
                 : "=r"(r0), "=r"(r1), "=r"(r2), "=r"(r3) : "r"(a));
}

static __device__ __forceinline__ void mma16816(float& d0, float& d1, float& d2, float& d3,
                                                uint32_t a0, uint32_t a1, uint32_t a2, uint32_t a3,
                                                uint32_t b0, uint32_t b1) {
    asm volatile("mma.sync.aligned.m16n8k16.row.col.f32.f16.f16.f32 "
                 "{%0,%1,%2,%3}, {%4,%5,%6,%7}, {%8,%9}, {%0,%1,%2,%3};"
                 : "+f"(d0), "+f"(d1), "+f"(d2), "+f"(d3)
                 : "r"(a0), "r"(a1), "r"(a2), "r"(a3), "r"(b0), "r"(b1));
}

// round-to-nearest-even via magic number (valid for |x| < 2^22)
static __device__ __forceinline__ float rne(float x) {
    return (x + 12582912.0f) - 12582912.0f;
}

// Fused kernel. grid = (1024 rows i, 2 d-blocks, B); block = 256 threads.
// Thread tid generates features for pair (i, j), j = (i + dbase + tid + 1) mod 1024,
// into SMEM row tid. One early block barrier (weights tile); afterwards each warp
// is independent: features -> __syncwarp -> ldmatrix -> HMMA -> stores.
// Covers every off-diagonal unordered pair once (distance-512 twice, bitwise identical);
// writes out[i,j,:] and out[j,i,:]. Diagonal written by d-block 0.
__global__ __launch_bounds__(TPB)
void relbias_kernel(const float* __restrict__ vec,  // [B,1024,3]
                    const float* __restrict__ W,    // [64,16]
                    const float* __restrict__ bias, // [16]
                    float* __restrict__ out) {
    __shared__ __align__(16) uint8_t sA[TPB * ASTRIDE]; // fp16 features, row = pair
    __shared__ __align__(16) uint8_t sW[16 * ASTRIDE];  // fp16 weights [n][f']

    int tid = threadIdx.x;
    int i     = blockIdx.x;
    int dbase = blockIdx.y << 8;
    int b     = blockIdx.z;
    long long bb = (long long)b * NPTS;

    // W[64,16] fp32 -> sW[n][f'] fp16, f' interleaved: f'=2k -> Ws[k], f'=2k+1 -> Wc[k]
    for (int idx = tid; idx < 64 * 16; idx += TPB) {
        int n = idx & 15, k = idx >> 4;
        int fp = (k < 32) ? (2 * k) : (2 * (k - 32) + 1);
        *(__half*)(sW + n * ASTRIDE + fp * 2) = __float2half_rn(W[idx]);
    }
    // diagonal (exact fp32): out[b,i,i,:] = bias + sum_k Wc[k,:]
    if (blockIdx.y == 0 && tid < NH) {
        float a = bias[tid];
#pragma unroll
        for (int k = 0; k < 32; ++k) a += W[(32 + k) * NH + tid];
        out[((bb + i) * NPTS + i) * NH + tid] = a;
    }
    __syncthreads();   // the ONLY block-wide barrier (sW ready; drains STS)

    // ---- per-thread pair: angle + fp16 feature generation into SMEM row tid ----
    int j = (i + dbase + tid + 1) & (NPTS - 1);
    const float* vb = vec + (size_t)b * NPTS * 3;
    float ax = vb[i * 3 + 0], ay = vb[i * 3 + 1], az = vb[i * 3 + 2];
    float bx = vb[j * 3 + 0], by = vb[j * 3 + 1], bz = vb[j * 3 + 2];
    float ra = rsqrtf(ax * ax + ay * ay + az * az);
    float rb = rsqrtf(bx * bx + by * by + bz * bz);
    float dx = ax * ra - bx * rb;
    float dy = ay * ra - by * rb;
    float dz = az * ra - bz * rb;
    float dot = 1.0f - 0.5f * ((dx * dx + dy * dy) + dz * dz);
    dot = fminf(fmaxf(dot, -1.0f), 1.0f);
    float t = acosf(dot) * 200.0f * (10.0f / 31.0f);

    // fp32 Cody-Waite mod 2*pi (magic-number rounding)
    float q  = rne(t * 0.15915494309189535f);
    float tr = fmaf(q, -6.28125f, t);
    tr = fmaf(q, -1.9353071795864769e-3f, tr);
    float s1 = __sinf(tr), c1 = __cosf(tr);
    // mid-chain anchor at k=16
    float t16 = 16.0f * tr;
    float q2  = rne(t16 * 0.15915494309189535f);
    float tr16 = fmaf(q2, -6.28125f, t16);
    tr16 = fmaf(q2, -1.9353071795864769e-3f, tr16);
    float s16 = __sinf(tr16), c16 = __cosf(tr16);

    {
        float s = 0.0f, c = 1.0f;
        uint32_t buf[4];
#pragma unroll
        for (int k = 0; k < 32; ++k) {
            __half2 h2 = __floats2half2_rn(s, c);    // low = sin (f'=2k), high = cos (f'=2k+1)
            buf[k & 3] = *reinterpret_cast<uint32_t*>(&h2);
            if ((k & 3) == 3) {
                *(uint4*)(sA + tid * ASTRIDE + (k >> 2) * 16) =
                    make_uint4(buf[0], buf[1], buf[2], buf[3]);
            }
            float ns = fmaf(s, c1, c * s1);
            float nc = fmaf(c, c1, -(s * s1));
            s = ns; c = nc;
            if (k == 15) { s = s16; c = c16; }       // re-anchor, halves drift
        }
    }

    __syncwarp();   // warp-local: this warp's 32 A-rows are ready

    // ---- HMMA: each warp computes its own 32 pairs x 16 heads ----
    int wid = tid >> 5, lane = tid & 31;
    int wbase = wid << 5;

    // B fragments from sW (ready since block barrier): bfrag[ntile][ktile][2]
    uint32_t bfrag[2][4][2];
    uint32_t sWb = smem_addr(sW);
#pragma unroll
    for (int nt = 0; nt < 2; ++nt) {
#pragma unroll
        for (int ktp = 0; ktp < 2; ++ktp) {
            uint32_t a = sWb + (uint32_t)(nt * 8 + (lane & 7)) * ASTRIDE
                       + (uint32_t)ktp * 64 + (uint32_t)(lane >> 3) * 16;
            ldsm_x4(bfrag[nt][2 * ktp][0], bfrag[nt][2 * ktp][1],
                    bfrag[nt][2 * ktp + 1][0], bfrag[nt][2 * ktp + 1][1], a);
        }
    }

    float acc[2][2][4];
#pragma unroll
    for (int mt = 0; mt < 2; ++mt)
#pragma unroll
        for (int nt = 0; nt < 2; ++nt)
#pragma unroll
            for (int e = 0; e < 4; ++e) acc[mt][nt][e] = 0.0f;

    uint32_t sAb = smem_addr(sA);
#pragma unroll
    for (int mt = 0; mt < 2; ++mt) {
#pragma unroll
        for (int kt = 0; kt < 4; ++kt) {
            uint32_t a = sAb + (uint32_t)(wbase + mt * 16 + (lane & 15)) * ASTRIDE
                       + (uint32_t)kt * 32 + (uint32_t)(lane >> 4) * 16;
            uint32_t a0, a1, a2, a3;
            ldsm_x4(a0, a1, a2, a3, a);
#pragma unroll
            for (int nt = 0; nt < 2; ++nt)
                mma16816(acc[mt][nt][0], acc[mt][nt][1], acc[mt][nt][2], acc[mt][nt][3],
                         a0, a1, a2, a3, bfrag[nt][kt][0], bfrag[nt][kt][1]);
        }
    }

    // ---- epilogue: bias + bfly-shuffle into float4, symmetric STG.128 ----
    int c4 = lane & 3;
    float2 bz0 = *(const float2*)(bias + 2 * c4);       // cols for nt=0
    float2 bz1 = *(const float2*)(bias + 8 + 2 * c4);   // cols for nt=1
    int colbase = (c4 & 1) * 8 + (c4 & 2) * 2;           // c0:0 c1:8 c2:4 c3:12

#pragma unroll
    for (int mt = 0; mt < 2; ++mt) {
#pragma unroll
        for (int h = 0; h < 2; ++h) {
            float2 v0 = make_float2(acc[mt][0][2 * h] + bz0.x, acc[mt][0][2 * h + 1] + bz0.y);
            float2 v1 = make_float2(acc[mt][1][2 * h] + bz1.x, acc[mt][1][2 * h + 1] + bz1.y);
            // even lanes send nt1, odd lanes send nt0; exchange with lane^1
            float2 snd = (c4 & 1) ? v0 : v1;
            double sd = *reinterpret_cast<double*>(&snd);
            double rd = __shfl_xor_sync(0xffffffffu, sd, 1);
            float2 rcv = *reinterpret_cast<float2*>(&rd);
            float4 res = (c4 & 1) ? make_float4(rcv.x, rcv.y, v1.x, v1.y)
                                  : make_float4(v0.x, v0.y, rcv.x, rcv.y);
            int p  = wbase + mt * 16 + h * 8 + (lane >> 2);
            int jp = (i + dbase + p + 1) & (NPTS - 1);
            __stcs((float4*)(out + ((bb + i) * NPTS + jp) * NH + colbase), res);
            __stcs((float4*)(out + ((bb + jp) * NPTS + i) * NH + colbase), res);
        }
    }
}

extern "C" void kernel_launch(void* const* d_in, const int* in_sizes, int n_in,
                              void* d_out, int out_size) {
    const float* vec_map = (const float*)d_in[0];
    const float* kernelW = (const float*)d_in[1];
    const float* bias    = (const float*)d_in[2];
    float* out = (float*)d_out;

    int total_vecs = in_sizes[0] / 3;   // B * N
    int B = total_vecs / NPTS;

    dim3 grid(NPTS, 2, B);
    relbias_kernel<<<grid, TPB>>>(vec_map, kernelW, bias, out);
}